// round 1
// baseline (speedup 1.0000x reference)
#include <cuda_runtime.h>
#include <cuda_bf16.h>

// Embedding gather: out[t, :] = W_E[tokens[t], :]
// tokens: int32 [32768]   (d_in[0])
// W_E:    float32 [50257, 768]  (d_in[1])
// out:    float32 [32768, 768]
//
// One CTA per token, 192 threads, each thread copies one float4 (16 B).
// Pure memory-bound streaming gather; target HBM roofline (~192 MiB total traffic).

#define D_MODEL 768
#define V4 (D_MODEL / 4)   // 192 float4 per row

__global__ __launch_bounds__(V4) void embed_gather_kernel(
    const int* __restrict__ tokens,
    const float4* __restrict__ W,
    float4* __restrict__ out)
{
    const int tok_idx = blockIdx.x;
    const int col = threadIdx.x;
    const int row = __ldg(tokens + tok_idx);   // uniform per block, L1 broadcast
    out[(size_t)tok_idx * V4 + col] = __ldg(W + (size_t)row * V4 + col);
}

extern "C" void kernel_launch(void* const* d_in, const int* in_sizes, int n_in,
                              void* d_out, int out_size)
{
    const int* tokens = (const int*)d_in[0];
    const float4* W   = (const float4*)d_in[1];
    float4* out       = (float4*)d_out;

    const int n_tok = in_sizes[0];   // 8 * 4096 = 32768

    embed_gather_kernel<<<n_tok, V4>>>(tokens, W, out);
}

// round 2
// speedup vs baseline: 1.1624x; 1.1624x over previous
#include <cuda_runtime.h>
#include <cuda_bf16.h>

// Embedding gather: out[t, :] = W_E[tokens[t], :]
// tokens: int32 [32768]   (d_in[0])
// W_E:    float32 [50257, 768]  (d_in[1])
// out:    float32 [32768, 768]
//
// R1 -> R2: was latency-limited (DRAM 50.7%, MLP=1/thread). Now each CTA of
// 192 threads handles U=8 tokens: batch 8 independent token loads, then 8
// independent 128B row loads, then 8 stores. 8x read MLP per warp.

#define D_MODEL 768
#define V4 (D_MODEL / 4)   // 192 float4 per row
#define U 8                // tokens per CTA

__global__ __launch_bounds__(V4) void embed_gather_kernel(
    const int* __restrict__ tokens,
    const float4* __restrict__ W,
    float4* __restrict__ out,
    int n_tok)
{
    const int col = threadIdx.x;
    const int t0  = blockIdx.x * U;

    if (t0 + U <= n_tok) {
        // fast path: full group of U tokens
        int rows[U];
#pragma unroll
        for (int u = 0; u < U; ++u)
            rows[u] = __ldg(tokens + t0 + u);       // independent, L2-hot

        float4 v[U];
#pragma unroll
        for (int u = 0; u < U; ++u)
            v[u] = __ldg(W + (size_t)rows[u] * V4 + col);   // 8 independent 128B loads

#pragma unroll
        for (int u = 0; u < U; ++u)
            out[(size_t)(t0 + u) * V4 + col] = v[u];
    } else {
        for (int t = t0; t < n_tok; ++t) {
            int row = __ldg(tokens + t);
            out[(size_t)t * V4 + col] = __ldg(W + (size_t)row * V4 + col);
        }
    }
}

extern "C" void kernel_launch(void* const* d_in, const int* in_sizes, int n_in,
                              void* d_out, int out_size)
{
    const int* tokens = (const int*)d_in[0];
    const float4* W   = (const float4*)d_in[1];
    float4* out       = (float4*)d_out;

    const int n_tok = in_sizes[0];   // 32768
    const int grid  = (n_tok + U - 1) / U;

    embed_gather_kernel<<<grid, V4>>>(tokens, W, out, n_tok);
}

// round 4
// speedup vs baseline: 1.1702x; 1.0067x over previous
#include <cuda_runtime.h>
#include <cuda_bf16.h>
#include <cstdint>

// Embedding gather: out[t, :] = W_E[tokens[t], :]
// tokens: int32 [32768], W_E: float32 [50257, 768], out: float32 [32768, 768]
//
// R3 -> R4: R3 never launched (dynamic 48KB + static smem exceeded the default
// 48KB block limit -> sticky launch error -> capture failed). Fix: G=14 rows
// (43KB dynamic), add fence.proxy.async after mbarrier.init, and double-buffer
// (two mbarriers, 7 rows each) so bulk stores of half A overlap loads of half B.
// Per-CTA in flight: 43KB; 5 CTAs/SM -> ~215KB/SM outstanding.

#define D_MODEL   768
#define ROW_BYTES (D_MODEL * 4)     // 3072
#define G         14                // tokens per CTA
#define GH        (G / 2)           // 7 per half
#define SMEM_BYTES (G * ROW_BYTES)  // 43008 B

__device__ __forceinline__ uint32_t smem_u32(const void* p) {
    uint32_t a;
    asm("{ .reg .u64 t; cvta.to.shared.u64 t, %1; cvt.u32.u64 %0, t; }"
        : "=r"(a) : "l"(p));
    return a;
}

__device__ __forceinline__ void mbar_wait(uint32_t mbar_a) {
    asm volatile(
        "{\n\t"
        ".reg .pred P1;\n\t"
        "WAIT_LOOP_%=:\n\t"
        "mbarrier.try_wait.parity.shared.b64 P1, [%0], 0, 0x989680;\n\t"
        "@P1 bra.uni WAIT_DONE_%=;\n\t"
        "bra.uni WAIT_LOOP_%=;\n\t"
        "WAIT_DONE_%=:\n\t"
        "}"
        :: "r"(mbar_a) : "memory");
}

__global__ __launch_bounds__(32) void embed_bulk_kernel(
    const int* __restrict__ tokens,
    const unsigned char* __restrict__ W,     // byte view of W_E
    unsigned char* __restrict__ out,         // byte view of out
    int n_tok)
{
    extern __shared__ __align__(128) unsigned char sbuf[];
    __shared__ __align__(16) uint64_t mbar[2];
    __shared__ int srows[G];

    const int tid = threadIdx.x;
    const int t0  = blockIdx.x * G;
    const int cnt = (n_tok - t0 < G) ? (n_tok - t0) : G;

    if (tid < cnt)
        srows[tid] = __ldg(tokens + t0 + tid);

    const uint32_t mbarA = smem_u32(&mbar[0]);
    const uint32_t mbarB = smem_u32(&mbar[1]);
    if (tid == 0) {
        asm volatile("mbarrier.init.shared.b64 [%0], 1;" :: "r"(mbarA) : "memory");
        asm volatile("mbarrier.init.shared.b64 [%0], 1;" :: "r"(mbarB) : "memory");
        asm volatile("fence.proxy.async.shared::cta;" ::: "memory");
    }
    __syncwarp();

    if (tid == 0) {
        const uint32_t sbase = smem_u32(sbuf);
        const int cntA = (cnt < GH) ? cnt : GH;   // rows [0, cntA)
        const int cntB = cnt - cntA;              // rows [GH, GH+cntB)

        // Arm both barriers with their byte counts.
        asm volatile("mbarrier.arrive.expect_tx.shared.b64 _, [%0], %1;"
                     :: "r"(mbarA), "r"((uint32_t)(cntA * ROW_BYTES)) : "memory");
        asm volatile("mbarrier.arrive.expect_tx.shared.b64 _, [%0], %1;"
                     :: "r"(mbarB), "r"((uint32_t)(cntB * ROW_BYTES)) : "memory");

        // Issue all bulk loads (independent, fully in flight).
        #pragma unroll
        for (int g = 0; g < G; ++g) {
            if (g < cnt) {
                const unsigned char* src = W + (size_t)srows[g] * ROW_BYTES;
                const uint32_t bar = (g < GH) ? mbarA : mbarB;
                asm volatile(
                    "cp.async.bulk.shared::cta.global.mbarrier::complete_tx::bytes "
                    "[%0], [%1], %2, [%3];"
                    :: "r"(sbase + g * ROW_BYTES), "l"(src),
                       "r"((uint32_t)ROW_BYTES), "r"(bar)
                    : "memory");
            }
        }

        // Half A: wait, then start stores while half B still lands.
        mbar_wait(mbarA);
        #pragma unroll
        for (int g = 0; g < GH; ++g) {
            if (g < cnt) {
                unsigned char* dst = out + (size_t)(t0 + g) * ROW_BYTES;
                asm volatile(
                    "cp.async.bulk.global.shared::cta.bulk_group [%0], [%1], %2;"
                    :: "l"(dst), "r"(sbase + g * ROW_BYTES),
                       "r"((uint32_t)ROW_BYTES)
                    : "memory");
            }
        }
        asm volatile("cp.async.bulk.commit_group;" ::: "memory");

        // Half B.
        mbar_wait(mbarB);
        #pragma unroll
        for (int g = GH; g < G; ++g) {
            if (g < cnt) {
                unsigned char* dst = out + (size_t)(t0 + g) * ROW_BYTES;
                asm volatile(
                    "cp.async.bulk.global.shared::cta.bulk_group [%0], [%1], %2;"
                    :: "l"(dst), "r"(sbase + g * ROW_BYTES),
                       "r"((uint32_t)ROW_BYTES)
                    : "memory");
            }
        }
        asm volatile("cp.async.bulk.commit_group;" ::: "memory");
        asm volatile("cp.async.bulk.wait_group 0;" ::: "memory");
    }
}

extern "C" void kernel_launch(void* const* d_in, const int* in_sizes, int n_in,
                              void* d_out, int out_size)
{
    const int* tokens      = (const int*)d_in[0];
    const unsigned char* W = (const unsigned char*)d_in[1];
    unsigned char* out     = (unsigned char*)d_out;

    const int n_tok = in_sizes[0];               // 32768
    const int grid  = (n_tok + G - 1) / G;       // 2341

    embed_bulk_kernel<<<grid, 32, SMEM_BYTES>>>(tokens, W, out, n_tok);
}